// round 4
// baseline (speedup 1.0000x reference)
#include <cuda_runtime.h>
#include <cstdint>

#define NPTS 4096
#define CCH  128
#define BB   2
#define KNB  9
#define OC   256
#define OC2  512

#define RT   32    // rows per knn block
#define MT   128   // cols per knn chunk

// -------- scratch (no allocation allowed) --------
__device__ float g_xn[(size_t)BB*CCH*NPTS];        // normalized features, (B,C,N)
__device__ float g_sq[BB*NPTS];                    // squared norms of normalized pts
__device__ float g_wct[CCH*OC2];                   // [c][o]: o<256 -> w1-w2, else w2
__device__ float g_y[(size_t)BB*NPTS*OC2];         // (B,N,512): [:,:,0:256]=p, [256:512]=q
__device__ int   g_nn[BB*NPTS*KNB];                // knn indices

// ---------------- prep: normalize + sq ----------------
__global__ void prep_kernel(const float* __restrict__ x) {
    int b = blockIdx.y;
    int n = blockIdx.x * 128 + threadIdx.x;
    const float* xb = x + (size_t)b * CCH * NPTS;
    float s = 0.f;
    #pragma unroll 8
    for (int c = 0; c < CCH; ++c) { float v = xb[c * NPTS + n]; s = fmaf(v, v, s); }
    float inv = rsqrtf(s + 1e-12f);
    g_sq[b * NPTS + n] = s * inv * inv;
    float* xnb = g_xn + (size_t)b * CCH * NPTS;
    #pragma unroll 8
    for (int c = 0; c < CCH; ++c) xnb[c * NPTS + n] = xb[c * NPTS + n] * inv;
}

// ---------------- prep: build combined weight [c][512] ----------------
__global__ void wprep_kernel(const float* __restrict__ w) {
    int i = blockIdx.x * 256 + threadIdx.x;
    if (i >= CCH * OC2) return;
    int c = i / OC2, o = i % OC2;
    float v;
    if (o < OC) v = w[o * 256 + c] - w[o * 256 + 128 + c];   // w1 - w2
    else        v = w[(o - OC) * 256 + 128 + c];             // w2
    g_wct[i] = v;
}

// ---------------- knn: tiled inner-product + fused top-9 ----------------
__device__ __forceinline__ unsigned long long packKey(float v, unsigned idx) {
    unsigned u = __float_as_uint(v);
    u = (u & 0x80000000u) ? ~u : (u | 0x80000000u);   // order-preserving float->uint
    return ((unsigned long long)u << 32) | (0xFFFFFFFFu - idx); // lower idx wins ties
}

__global__ void __launch_bounds__(256, 2)
knn_kernel() {
    extern __shared__ float sm[];
    float* An  = sm;                         // [128][32]
    float* Bm  = An  + CCH * RT;             // [128][128]
    float* Ssc = Bm  + CCH * MT;             // [32][132]
    float* sqm = Ssc + RT * (MT + 4);        // [128]
    float* sqr = sqm + MT;                   // [32]

    const int tid = threadIdx.x;
    const int b   = blockIdx.y;
    const int n0  = blockIdx.x * RT;
    const float* xnb = g_xn + (size_t)b * CCH * NPTS;

    // load row block once (fixed for the whole kernel)
    for (int i = tid; i < CCH * RT; i += 256) {
        int c = i >> 5, r = i & 31;
        An[c * RT + r] = xnb[c * NPTS + n0 + r];
    }
    if (tid < RT) sqr[tid] = g_sq[b * NPTS + n0 + tid];

    const int tr = tid >> 5;   // phase A: row group (0..7), constant per warp
    const int tc = tid & 31;   // phase A: col group
    const int rB = tid >> 3;   // phase B: owned row (0..31)
    const int cs = tid & 7;    // phase B: col slice (16 cols)

    unsigned long long t[9];
    #pragma unroll
    for (int i = 0; i < 9; ++i) t[i] = 0ull;

    __syncthreads();
    const float sq_n = sqr[rB];

    for (int chunk = 0; chunk < NPTS / MT; ++chunk) {
        const int m0 = chunk * MT;
        for (int i = tid; i < CCH * MT; i += 256) {
            int c = i >> 7, m = i & 127;
            Bm[c * MT + m] = xnb[c * NPTS + m0 + m];
        }
        if (tid < MT) sqm[tid] = g_sq[b * NPTS + m0 + tid];
        __syncthreads();

        // phase A: 32x128 inner-product tile, 4x4 micro-tile per thread
        float acc[4][4];
        #pragma unroll
        for (int i = 0; i < 4; ++i)
            #pragma unroll
            for (int j = 0; j < 4; ++j) acc[i][j] = 0.f;

        const float* Ap = &An[tr * 4];
        const float* Bp = &Bm[tc * 4];
        #pragma unroll 4
        for (int c = 0; c < CCH; ++c) {
            float4 a = *(const float4*)(Ap + c * RT);
            float4 v = *(const float4*)(Bp + c * MT);
            acc[0][0]=fmaf(a.x,v.x,acc[0][0]); acc[0][1]=fmaf(a.x,v.y,acc[0][1]);
            acc[0][2]=fmaf(a.x,v.z,acc[0][2]); acc[0][3]=fmaf(a.x,v.w,acc[0][3]);
            acc[1][0]=fmaf(a.y,v.x,acc[1][0]); acc[1][1]=fmaf(a.y,v.y,acc[1][1]);
            acc[1][2]=fmaf(a.y,v.z,acc[1][2]); acc[1][3]=fmaf(a.y,v.w,acc[1][3]);
            acc[2][0]=fmaf(a.z,v.x,acc[2][0]); acc[2][1]=fmaf(a.z,v.y,acc[2][1]);
            acc[2][2]=fmaf(a.z,v.z,acc[2][2]); acc[2][3]=fmaf(a.z,v.w,acc[2][3]);
            acc[3][0]=fmaf(a.w,v.x,acc[3][0]); acc[3][1]=fmaf(a.w,v.y,acc[3][1]);
            acc[3][2]=fmaf(a.w,v.z,acc[3][2]); acc[3][3]=fmaf(a.w,v.w,acc[3][3]);
        }
        #pragma unroll
        for (int i = 0; i < 4; ++i) {
            float4 v = make_float4(acc[i][0], acc[i][1], acc[i][2], acc[i][3]);
            *(float4*)&Ssc[(tr * 4 + i) * (MT + 4) + tc * 4] = v;
        }
        __syncthreads();

        // phase B: per-thread top-9 over its 16 cols of its row
        #pragma unroll
        for (int j = 0; j < 16; ++j) {
            int m = cs * 16 + j;
            float inner = Ssc[rB * (MT + 4) + m];
            float val = 2.f * inner - sq_n - sqm[m];
            unsigned long long key = packKey(val, (unsigned)(m0 + m));
            if (key > t[8]) {
                #pragma unroll
                for (int i = 0; i < 9; ++i) {
                    unsigned long long a = t[i];
                    bool g = key > a;
                    t[i] = g ? key : a;
                    key  = g ? a : key;
                }
            }
        }
        __syncthreads();
    }

    // merge top-9 across the 8 threads owning each row (8-lane shfl segments)
    const int row = n0 + rB;
    for (int k = 0; k < KNB; ++k) {
        unsigned long long m = t[0];
        #pragma unroll
        for (int d = 4; d; d >>= 1) {
            unsigned long long o = __shfl_down_sync(0xffffffffu, m, d, 8);
            if (o > m) m = o;
        }
        m = __shfl_sync(0xffffffffu, m, 0, 8);   // broadcast segment max
        if (t[0] == m) {                          // exactly one lane (keys unique)
            #pragma unroll
            for (int i = 0; i < 8; ++i) t[i] = t[i + 1];
            t[8] = 0ull;
        }
        if (cs == 0)
            g_nn[(b * NPTS + row) * KNB + k] = (int)(0xFFFFFFFFu - (unsigned)m);
    }
}

// ---------------- fused p/q GEMM: y[b][n][o] = sum_c x[b][c][n] * wct[c][o] ----------------
#define GT 64
__global__ void __launch_bounds__(256)
gemm_kernel(const float* __restrict__ x) {
    extern __shared__ float sm[];
    float* Xs = sm;               // [128][64]
    float* Ws = sm + CCH * GT;    // [128][64]
    const int tid = threadIdx.x;
    const int b  = blockIdx.z;
    const int n0 = blockIdx.x * GT;
    const int o0 = blockIdx.y * GT;
    const float* xb = x + (size_t)b * CCH * NPTS;

    for (int i = tid; i < CCH * GT; i += 256) {
        int c = i >> 6, nn = i & 63;
        Xs[c * GT + nn] = xb[c * NPTS + n0 + nn];
    }
    for (int i = tid; i < CCH * GT; i += 256) {
        int c = i >> 6, oo = i & 63;
        Ws[c * GT + oo] = g_wct[c * OC2 + o0 + oo];
    }
    __syncthreads();

    const int tn = (tid & 15) * 4;
    const int to = (tid >> 4) * 4;
    float acc[4][4];
    #pragma unroll
    for (int i = 0; i < 4; ++i)
        #pragma unroll
        for (int j = 0; j < 4; ++j) acc[i][j] = 0.f;

    #pragma unroll 4
    for (int c = 0; c < CCH; ++c) {
        float4 xa = *(const float4*)&Xs[c * GT + tn];
        float4 wa = *(const float4*)&Ws[c * GT + to];
        acc[0][0]=fmaf(xa.x,wa.x,acc[0][0]); acc[0][1]=fmaf(xa.x,wa.y,acc[0][1]);
        acc[0][2]=fmaf(xa.x,wa.z,acc[0][2]); acc[0][3]=fmaf(xa.x,wa.w,acc[0][3]);
        acc[1][0]=fmaf(xa.y,wa.x,acc[1][0]); acc[1][1]=fmaf(xa.y,wa.y,acc[1][1]);
        acc[1][2]=fmaf(xa.y,wa.z,acc[1][2]); acc[1][3]=fmaf(xa.y,wa.w,acc[1][3]);
        acc[2][0]=fmaf(xa.z,wa.x,acc[2][0]); acc[2][1]=fmaf(xa.z,wa.y,acc[2][1]);
        acc[2][2]=fmaf(xa.z,wa.z,acc[2][2]); acc[2][3]=fmaf(xa.z,wa.w,acc[2][3]);
        acc[3][0]=fmaf(xa.w,wa.x,acc[3][0]); acc[3][1]=fmaf(xa.w,wa.y,acc[3][1]);
        acc[3][2]=fmaf(xa.w,wa.z,acc[3][2]); acc[3][3]=fmaf(xa.w,wa.w,acc[3][3]);
    }

    float* yb = g_y + (size_t)b * NPTS * OC2;
    #pragma unroll
    for (int i = 0; i < 4; ++i) {
        float4 v = make_float4(acc[i][0], acc[i][1], acc[i][2], acc[i][3]);
        *(float4*)&yb[(size_t)(n0 + tn + i) * OC2 + o0 + to] = v;
    }
}

// ---------------- epilogue: gather + max + relu ----------------
__global__ void final_kernel(const float* __restrict__ bias, float* __restrict__ out) {
    __shared__ int sj[KNB];
    const int n = blockIdx.x;
    const int b = blockIdx.y;
    const int o = threadIdx.x;
    if (o < KNB) sj[o] = g_nn[(b * NPTS + n) * KNB + o];
    __syncthreads();
    const float* yb = g_y + (size_t)b * NPTS * OC2;
    float p = yb[(size_t)n * OC2 + o];
    float best = -3.4e38f;
    #pragma unroll
    for (int k = 0; k < KNB; ++k)
        best = fmaxf(best, yb[(size_t)sj[k] * OC2 + OC + o]);
    float v = fmaxf(p + best + bias[o], 0.f);
    out[((size_t)b * OC + o) * NPTS + n] = v;
}

// ---------------- launch ----------------
extern "C" void kernel_launch(void* const* d_in, const int* in_sizes, int n_in,
                              void* d_out, int out_size) {
    const float* x    = (const float*)d_in[0];
    const float* w    = (const float*)d_in[1];
    const float* bias = (const float*)d_in[2];
    float* out = (float*)d_out;

    const int knn_smem  = (CCH*RT + CCH*MT + RT*(MT+4) + MT + RT) * (int)sizeof(float); // 99456
    const int gemm_smem = 2 * CCH * GT * (int)sizeof(float);                            // 65536
    cudaFuncSetAttribute(knn_kernel,  cudaFuncAttributeMaxDynamicSharedMemorySize, knn_smem);
    cudaFuncSetAttribute(gemm_kernel, cudaFuncAttributeMaxDynamicSharedMemorySize, gemm_smem);

    prep_kernel <<<dim3(NPTS / 128, BB), 128>>>(x);
    wprep_kernel<<<(CCH * OC2 + 255) / 256, 256>>>(w);
    knn_kernel  <<<dim3(NPTS / RT, BB), 256, knn_smem>>>();
    gemm_kernel <<<dim3(NPTS / GT, OC2 / GT, BB), 256, gemm_smem>>>(x);
    final_kernel<<<dim3(NPTS, BB), 256>>>(bias, out);
}

// round 6
// speedup vs baseline: 1.6440x; 1.6440x over previous
#include <cuda_runtime.h>
#include <cuda_bf16.h>
#include <cstdint>

#define NPTS 4096
#define CCH  128
#define BB   2
#define KNB  9
#define OC   256
#define OC2  512

// knn tiling
#define KM   64            // rows per block
#define KN   128           // cols per chunk
#define KSTR 264           // smem row stride in bf16 (256 data + 8 pad) = 528B
#define KWST 132           // same stride in 32-bit words
#define SSTR 132           // score row stride (floats)

// -------- scratch (no allocation allowed) --------
__device__ __nv_bfloat16 g_ab[(size_t)BB*NPTS*256];  // per point: [hi(128) | lo(128)]
__device__ float g_sq[BB*NPTS];                      // squared norms of normalized pts
__device__ float g_wct[CCH*OC2];                     // [c][o]: o<256 -> w1-w2, else w2
__device__ float g_y[(size_t)BB*NPTS*OC2];           // (B,N,512): [0:256]=p, [256:512]=q
__device__ int   g_nn[BB*NPTS*KNB];                  // knn indices

// ---------------- prep: normalize, split to bf16 hi/lo (transposed), sq ----------------
__global__ void __launch_bounds__(128) prep_kernel(const float* __restrict__ x) {
    extern __shared__ float psm[];
    float* sm   = psm;            // [128][129]
    float* invs = psm + 128*129;  // [128]
    const int b = blockIdx.y, n0 = blockIdx.x * 128, tid = threadIdx.x;
    const float* xb = x + (size_t)b * CCH * NPTS;

    for (int i = tid; i < 128 * 128; i += 128) {
        int c = i >> 7, n = i & 127;
        sm[c * 129 + n] = xb[c * NPTS + n0 + n];
    }
    __syncthreads();

    float s = 0.f;
    #pragma unroll 8
    for (int c = 0; c < 128; ++c) { float v = sm[c * 129 + tid]; s = fmaf(v, v, s); }
    float inv = rsqrtf(s + 1e-12f);
    g_sq[b * NPTS + n0 + tid] = s * inv * inv;
    invs[tid] = inv;
    __syncthreads();

    const int wid = tid >> 5, l = tid & 31;
    for (int p = wid; p < 128; p += 4) {
        float ip = invs[p];
        __nv_bfloat16 hi[4], lo[4];
        #pragma unroll
        for (int q = 0; q < 4; ++q) {
            float v = sm[(4 * l + q) * 129 + p] * ip;
            hi[q] = __float2bfloat16(v);
            lo[q] = __float2bfloat16(v - __bfloat162float(hi[q]));
        }
        __nv_bfloat16* dst = g_ab + (size_t)(b * NPTS + n0 + p) * 256;
        *(uint2*)(dst + 4 * l)       = *(uint2*)hi;
        *(uint2*)(dst + 128 + 4 * l) = *(uint2*)lo;
    }
}

// ---------------- prep: build combined weight [c][512] ----------------
__global__ void wprep_kernel(const float* __restrict__ w) {
    int i = blockIdx.x * 256 + threadIdx.x;
    if (i >= CCH * OC2) return;
    int c = i / OC2, o = i % OC2;
    float v;
    if (o < OC) v = w[o * 256 + c] - w[o * 256 + 128 + c];   // w1 - w2
    else        v = w[(o - OC) * 256 + 128 + c];             // w2
    g_wct[i] = v;
}

// ---------------- knn: tensor-core distance matrix + fused top-9 ----------------
__device__ __forceinline__ unsigned long long packKey(float v, unsigned idx) {
    unsigned u = __float_as_uint(v);
    u = (u & 0x80000000u) ? ~u : (u | 0x80000000u);   // order-preserving float->uint
    return ((unsigned long long)u << 32) | (0xFFFFFFFFu - idx);
}

__device__ __forceinline__ void mma_bf16(float* c,
        uint32_t a0, uint32_t a1, uint32_t a2, uint32_t a3,
        uint32_t b0, uint32_t b1) {
    asm volatile(
        "mma.sync.aligned.m16n8k16.row.col.f32.bf16.bf16.f32 "
        "{%0,%1,%2,%3},{%4,%5,%6,%7},{%8,%9},{%0,%1,%2,%3};"
        : "+f"(c[0]), "+f"(c[1]), "+f"(c[2]), "+f"(c[3])
        : "r"(a0), "r"(a1), "r"(a2), "r"(a3), "r"(b0), "r"(b1));
}

__global__ void __launch_bounds__(256, 1)
knn_kernel() {
    extern __shared__ char smraw[];
    __nv_bfloat16* As = (__nv_bfloat16*)smraw;        // [64][264]
    __nv_bfloat16* Bs = As + KM * KSTR;               // [128][264]
    float* Ssc = (float*)(Bs + KN * KSTR);            // [64][132]
    float* sqm = Ssc + KM * SSTR;                     // [128]
    float* sqr = sqm + KN;                            // [64]

    const int tid = threadIdx.x;
    const int b   = blockIdx.y;
    const int n0  = blockIdx.x * KM;
    const uint4* __restrict__ abG = (const uint4*)g_ab;   // 32 uint4 per point

    // load fixed row block (hi|lo), 16B vectors, padded rows (33 uint4/row)
    for (int i = tid; i < KM * 32; i += 256) {
        int r = i >> 5, j = i & 31;
        ((uint4*)As)[r * 33 + j] = abG[(size_t)(b * NPTS + n0 + r) * 32 + j];
    }
    if (tid < KM) sqr[tid] = g_sq[b * NPTS + n0 + tid];

    const int wid = tid >> 5, l = tid & 31;
    const int wm = wid & 1, wn = wid >> 1;   // 2x4 warp grid, warp tile 32x32
    const int g = l >> 2, t = l & 3;

    const int rB = tid >> 2, cs = tid & 3;   // phase B: 4 threads per row

    unsigned long long tk[9];
    #pragma unroll
    for (int i = 0; i < 9; ++i) tk[i] = 0ull;

    __syncthreads();
    const float sq_n = sqr[rB];

    const uint32_t* Asw = (const uint32_t*)As;
    const uint32_t* Bsw = (const uint32_t*)Bs;
    const int arBase = wm * 32 + g;          // A fragment row (+= mi*16, +8)
    const int bcBase = wn * 32 + g;          // B fragment col (+= ni*8)

    for (int chunk = 0; chunk < NPTS / KN; ++chunk) {
        const int m0 = chunk * KN;
        __syncthreads();   // previous phase-B readers done before overwriting Bs/Ssc
        for (int i = tid; i < KN * 32; i += 256) {
            int r = i >> 5, j = i & 31;
            ((uint4*)Bs)[r * 33 + j] = abG[(size_t)(b * NPTS + m0 + r) * 32 + j];
        }
        if (tid < KN) sqm[tid] = g_sq[b * NPTS + m0 + tid];
        __syncthreads();

        float acc[2][4][4];
        #pragma unroll
        for (int mi = 0; mi < 2; ++mi)
            #pragma unroll
            for (int ni = 0; ni < 4; ++ni)
                #pragma unroll
                for (int q = 0; q < 4; ++q) acc[mi][ni][q] = 0.f;

        // K=384 emulated-fp32: (hi,hi) + (hi,lo) + (lo,hi)
        #pragma unroll
        for (int seg = 0; seg < 3; ++seg) {
            const int aoff = (seg == 2) ? 64 : 0;   // word offsets (128 bf16 = 64 words)
            const int boff = (seg == 1) ? 64 : 0;
            #pragma unroll
            for (int kk = 0; kk < 8; ++kk) {
                const int ka = aoff + kk * 8 + t;
                const int kb = boff + kk * 8 + t;
                uint32_t a[2][4];
                #pragma unroll
                for (int mi = 0; mi < 2; ++mi) {
                    int r = arBase + mi * 16;
                    a[mi][0] = Asw[r * KWST + ka];
                    a[mi][1] = Asw[(r + 8) * KWST + ka];
                    a[mi][2] = Asw[r * KWST + ka + 4];
                    a[mi][3] = Asw[(r + 8) * KWST + ka + 4];
                }
                uint32_t bf[4][2];
                #pragma unroll
                for (int ni = 0; ni < 4; ++ni) {
                    int c = bcBase + ni * 8;
                    bf[ni][0] = Bsw[c * KWST + kb];
                    bf[ni][1] = Bsw[c * KWST + kb + 4];
                }
                #pragma unroll
                for (int mi = 0; mi < 2; ++mi)
                    #pragma unroll
                    for (int ni = 0; ni < 4; ++ni)
                        mma_bf16(acc[mi][ni], a[mi][0], a[mi][1], a[mi][2], a[mi][3],
                                 bf[ni][0], bf[ni][1]);
            }
        }

        // scatter fragments to score smem
        #pragma unroll
        for (int mi = 0; mi < 2; ++mi)
            #pragma unroll
            for (int ni = 0; ni < 4; ++ni) {
                int r = wm * 32 + mi * 16 + g;
                int c = wn * 32 + ni * 8 + t * 2;
                *(float2*)&Ssc[r * SSTR + c]       = make_float2(acc[mi][ni][0], acc[mi][ni][1]);
                *(float2*)&Ssc[(r + 8) * SSTR + c] = make_float2(acc[mi][ni][2], acc[mi][ni][3]);
            }
        __syncthreads();

        // per-thread top-9 over 32 cols of its row
        #pragma unroll 4
        for (int j = 0; j < 32; ++j) {
            int m = cs * 32 + j;
            float inner = Ssc[rB * SSTR + m];
            float val = fmaf(2.f, inner, -sq_n - sqm[m]);
            unsigned long long key = packKey(val, (unsigned)(m0 + m));
            if (key > tk[8]) {
                #pragma unroll
                for (int i = 0; i < 9; ++i) {
                    unsigned long long a = tk[i];
                    bool gr = key > a;
                    tk[i] = gr ? key : a;
                    key   = gr ? a : key;
                }
            }
        }
    }

    // merge top-9 across the 4 threads owning each row
    const int row = n0 + rB;
    for (int k = 0; k < KNB; ++k) {
        unsigned long long m = tk[0];
        #pragma unroll
        for (int d = 2; d; d >>= 1) {
            unsigned long long o = __shfl_down_sync(0xffffffffu, m, d, 4);
            if (o > m) m = o;
        }
        m = __shfl_sync(0xffffffffu, m, 0, 4);
        if (tk[0] == m) {   // keys unique (idx embedded): exactly one lane pops
            #pragma unroll
            for (int i = 0; i < 8; ++i) tk[i] = tk[i + 1];
            tk[8] = 0ull;
        }
        if (cs == 0)
            g_nn[(b * NPTS + row) * KNB + k] = (int)(0xFFFFFFFFu - (unsigned)m);
    }
}

// ---------------- fused p/q GEMM: y[b][n][o] = sum_c x[b][c][n] * wct[c][o] ----------------
#define YN 128
#define YO 64
__global__ void __launch_bounds__(128)
gemm_kernel(const float* __restrict__ x) {
    extern __shared__ float sm[];
    float* Xs = sm;               // [128 c][128 n]
    float* Ws = sm + CCH * YN;    // [128 c][64 o]
    const int tid = threadIdx.x;
    const int b  = blockIdx.z;
    const int n0 = blockIdx.x * YN;
    const int o0 = blockIdx.y * YO;
    const float* xb = x + (size_t)b * CCH * NPTS;

    for (int i = tid * 4; i < CCH * YN; i += 128 * 4) {
        int c = i >> 7, nn = i & 127;
        *(float4*)&Xs[i] = *(const float4*)&xb[c * NPTS + n0 + nn];
    }
    for (int i = tid * 4; i < CCH * YO; i += 128 * 4) {
        int c = i >> 6, oo = i & 63;
        *(float4*)&Ws[i] = *(const float4*)&g_wct[c * OC2 + o0 + oo];
    }
    __syncthreads();

    const int tn = (tid & 15) * 8;
    const int to = (tid >> 4) * 8;
    float acc[8][8];
    #pragma unroll
    for (int i = 0; i < 8; ++i)
        #pragma unroll
        for (int j = 0; j < 8; ++j) acc[i][j] = 0.f;

    #pragma unroll 2
    for (int c = 0; c < CCH; ++c) {
        float4 x0 = *(const float4*)&Xs[c * YN + tn];
        float4 x1 = *(const float4*)&Xs[c * YN + tn + 4];
        float4 w0 = *(const float4*)&Ws[c * YO + to];
        float4 w1 = *(const float4*)&Ws[c * YO + to + 4];
        float xa[8] = {x0.x, x0.y, x0.z, x0.w, x1.x, x1.y, x1.z, x1.w};
        float wa[8] = {w0.x, w0.y, w0.z, w0.w, w1.x, w1.y, w1.z, w1.w};
        #pragma unroll
        for (int i = 0; i < 8; ++i)
            #pragma unroll
            for (int j = 0; j < 8; ++j)
                acc[i][j] = fmaf(xa[i], wa[j], acc[i][j]);
    }

    float* yb = g_y + (size_t)b * NPTS * OC2;
    #pragma unroll
    for (int i = 0; i < 8; ++i) {
        float4 v0 = make_float4(acc[i][0], acc[i][1], acc[i][2], acc[i][3]);
        float4 v1 = make_float4(acc[i][4], acc[i][5], acc[i][6], acc[i][7]);
        *(float4*)&yb[(size_t)(n0 + tn + i) * OC2 + o0 + to]     = v0;
        *(float4*)&yb[(size_t)(n0 + tn + i) * OC2 + o0 + to + 4] = v1;
    }
}

// ---------------- epilogue: gather + max + relu ----------------
__global__ void final_kernel(const float* __restrict__ bias, float* __restrict__ out) {
    __shared__ int sj[KNB];
    const int n = blockIdx.x;
    const int b = blockIdx.y;
    const int o = threadIdx.x;
    if (o < KNB) sj[o] = g_nn[(b * NPTS + n) * KNB + o];
    __syncthreads();
    const float* yb = g_y + (size_t)b * NPTS * OC2;
    float p = yb[(size_t)n * OC2 + o];
    float best = -3.4e38f;
    #pragma unroll
    for (int k = 0; k < KNB; ++k)
        best = fmaxf(best, yb[(size_t)sj[k] * OC2 + OC + o]);
    float v = fmaxf(p + best + bias[o], 0.f);
    out[((size_t)b * OC + o) * NPTS + n] = v;
}

// ---------------- launch ----------------
extern "C" void kernel_launch(void* const* d_in, const int* in_sizes, int n_in,
                              void* d_out, int out_size) {
    const float* x    = (const float*)d_in[0];
    const float* w    = (const float*)d_in[1];
    const float* bias = (const float*)d_in[2];
    float* out = (float*)d_out;

    const int prep_smem = (128 * 129 + 128) * (int)sizeof(float);            // 66560
    const int knn_smem  = (KM + KN) * KSTR * 2 + (KM * SSTR + KN + KM) * 4;  // 135936
    const int gemm_smem = (CCH * YN + CCH * YO) * (int)sizeof(float);        // 98304
    cudaFuncSetAttribute(prep_kernel, cudaFuncAttributeMaxDynamicSharedMemorySize, prep_smem);
    cudaFuncSetAttribute(knn_kernel,  cudaFuncAttributeMaxDynamicSharedMemorySize, knn_smem);
    cudaFuncSetAttribute(gemm_kernel, cudaFuncAttributeMaxDynamicSharedMemorySize, gemm_smem);

    prep_kernel <<<dim3(NPTS / 128, BB), 128, prep_smem>>>(x);
    wprep_kernel<<<(CCH * OC2 + 255) / 256, 256>>>(w);
    knn_kernel  <<<dim3(NPTS / KM, BB), 256, knn_smem>>>();
    gemm_kernel <<<dim3(NPTS / YN, OC2 / YO, BB), 128, gemm_smem>>>(x);
    final_kernel<<<dim3(NPTS, BB), 256>>>(bias, out);
}

// round 7
// speedup vs baseline: 1.8726x; 1.1391x over previous
#include <cuda_runtime.h>
#include <cuda_bf16.h>
#include <cstdint>

#define NPTS 4096
#define CCH  128
#define BB   2
#define KNB  9
#define OC   256
#define OC2  512

// tiling (shared by knn + gemm)
#define KM   64            // rows per block
#define KN   128           // cols per chunk
#define KSTR 264           // smem row stride in bf16 (256 data + 8 pad) = 528B
#define KWST 132           // same stride in 32-bit words
#define SSTR 132           // score row stride (floats)

// -------- scratch (no allocation allowed) --------
__device__ __nv_bfloat16 g_ab[(size_t)BB*NPTS*256];  // per point: [hi(128) | lo(128)] of normalized x
__device__ __nv_bfloat16 g_wb[(size_t)OC2*256];      // per out-channel: [hi(128) | lo(128)] of wct
__device__ float g_sq[BB*NPTS];                      // squared norms of normalized pts
__device__ float g_nrm[BB*NPTS];                     // scale s*inv (~||x||)
__device__ float g_y[(size_t)BB*NPTS*OC2];           // (B,N,512): [0:256]=p, [256:512]=q
__device__ int   g_nn[BB*NPTS*KNB];                  // knn indices

#define CP_COMMIT() asm volatile("cp.async.commit_group;" ::: "memory")
#define CP_WAIT0()  asm volatile("cp.async.wait_group 0;" ::: "memory")
__device__ __forceinline__ void cp16(uint32_t dst, const void* src) {
    asm volatile("cp.async.cg.shared.global [%0], [%1], 16;" :: "r"(dst), "l"(src) : "memory");
}

// ---------------- prep: normalize, split to bf16 hi/lo (transposed), sq, nrm ----------------
__global__ void __launch_bounds__(128) prep_kernel(const float* __restrict__ x) {
    extern __shared__ float psm[];
    float* sm   = psm;            // [128][129]
    float* invs = psm + 128*129;  // [128]
    const int b = blockIdx.y, n0 = blockIdx.x * 128, tid = threadIdx.x;
    const float* xb = x + (size_t)b * CCH * NPTS;

    for (int i = tid; i < 128 * 128; i += 128) {
        int c = i >> 7, n = i & 127;
        sm[c * 129 + n] = xb[c * NPTS + n0 + n];
    }
    __syncthreads();

    float s = 0.f;
    #pragma unroll 8
    for (int c = 0; c < 128; ++c) { float v = sm[c * 129 + tid]; s = fmaf(v, v, s); }
    float inv = rsqrtf(s + 1e-12f);
    g_sq[b * NPTS + n0 + tid]  = s * inv * inv;
    g_nrm[b * NPTS + n0 + tid] = s * inv;        // xn * (s*inv) == x * (s*inv^2) ~= x
    invs[tid] = inv;
    __syncthreads();

    const int wid = tid >> 5, l = tid & 31;
    for (int p = wid; p < 128; p += 4) {
        float ip = invs[p];
        __nv_bfloat16 hi[4], lo[4];
        #pragma unroll
        for (int q = 0; q < 4; ++q) {
            float v = sm[(4 * l + q) * 129 + p] * ip;
            hi[q] = __float2bfloat16(v);
            lo[q] = __float2bfloat16(v - __bfloat162float(hi[q]));
        }
        __nv_bfloat16* dst = g_ab + (size_t)(b * NPTS + n0 + p) * 256;
        *(uint2*)(dst + 4 * l)       = *(uint2*)hi;
        *(uint2*)(dst + 128 + 4 * l) = *(uint2*)lo;
    }
}

// ---------------- prep: combined weight, bf16 hi/lo, layout [o][hi128|lo128] ----------------
__global__ void wprep_kernel(const float* __restrict__ w) {
    int i = blockIdx.x * 256 + threadIdx.x;
    if (i >= OC2 * CCH) return;
    int o = i >> 7, c = i & 127;
    float v;
    if (o < OC) v = w[o * 256 + c] - w[o * 256 + 128 + c];   // w1 - w2
    else        v = w[(o - OC) * 256 + 128 + c];             // w2
    __nv_bfloat16 hi = __float2bfloat16(v);
    __nv_bfloat16 lo = __float2bfloat16(v - __bfloat162float(hi));
    g_wb[(size_t)o * 256 + c]       = hi;
    g_wb[(size_t)o * 256 + 128 + c] = lo;
}

// ---------------- shared MMA helpers ----------------
__device__ __forceinline__ unsigned long long packKey(float v, unsigned idx) {
    unsigned u = __float_as_uint(v);
    u = (u & 0x80000000u) ? ~u : (u | 0x80000000u);   // order-preserving float->uint
    return ((unsigned long long)u << 32) | (0xFFFFFFFFu - idx);
}

__device__ __forceinline__ void mma_bf16(float* c,
        uint32_t a0, uint32_t a1, uint32_t a2, uint32_t a3,
        uint32_t b0, uint32_t b1) {
    asm volatile(
        "mma.sync.aligned.m16n8k16.row.col.f32.bf16.bf16.f32 "
        "{%0,%1,%2,%3},{%4,%5,%6,%7},{%8,%9},{%0,%1,%2,%3};"
        : "+f"(c[0]), "+f"(c[1]), "+f"(c[2]), "+f"(c[3])
        : "r"(a0), "r"(a1), "r"(a2), "r"(a3), "r"(b0), "r"(b1));
}

// emulated-fp32 K=384 MMA block: (hi,hi)+(hi,lo)+(lo,hi), acc[2][4][4]
__device__ __forceinline__ void mma_block(float acc[2][4][4],
        const uint32_t* Asw, const uint32_t* Bsw, int arBase, int bcBase, int t) {
    #pragma unroll
    for (int seg = 0; seg < 3; ++seg) {
        const int aoff = (seg == 2) ? 64 : 0;   // word offsets (128 bf16 = 64 words)
        const int boff = (seg == 1) ? 64 : 0;
        #pragma unroll
        for (int kk = 0; kk < 8; ++kk) {
            const int ka = aoff + kk * 8 + t;
            const int kb = boff + kk * 8 + t;
            uint32_t a[2][4];
            #pragma unroll
            for (int mi = 0; mi < 2; ++mi) {
                int r = arBase + mi * 16;
                a[mi][0] = Asw[r * KWST + ka];
                a[mi][1] = Asw[(r + 8) * KWST + ka];
                a[mi][2] = Asw[r * KWST + ka + 4];
                a[mi][3] = Asw[(r + 8) * KWST + ka + 4];
            }
            uint32_t bf[4][2];
            #pragma unroll
            for (int ni = 0; ni < 4; ++ni) {
                int c = bcBase + ni * 8;
                bf[ni][0] = Bsw[c * KWST + kb];
                bf[ni][1] = Bsw[c * KWST + kb + 4];
            }
            #pragma unroll
            for (int mi = 0; mi < 2; ++mi)
                #pragma unroll
                for (int ni = 0; ni < 4; ++ni)
                    mma_bf16(acc[mi][ni], a[mi][0], a[mi][1], a[mi][2], a[mi][3],
                             bf[ni][0], bf[ni][1]);
        }
    }
}

// ---------------- knn: pipelined tensor-core distance matrix + fused top-9 ----------------
__device__ __forceinline__ void knn_issueB(int b, int m0, uint32_t bsAddr, uint32_t sqmAddr, int tid) {
    const uint4* abG = (const uint4*)g_ab;
    #pragma unroll 4
    for (int i = tid; i < KN * 32; i += 256) {
        int r = i >> 5, j = i & 31;
        cp16(bsAddr + (unsigned)(r * 33 + j) * 16, abG + (size_t)(b * NPTS + m0 + r) * 32 + j);
    }
    if (tid < 32)
        cp16(sqmAddr + tid * 16, g_sq + b * NPTS + m0 + tid * 4);
    CP_COMMIT();
}

__global__ void __launch_bounds__(256, 1)
knn_kernel() {
    extern __shared__ char smraw[];
    __nv_bfloat16* As  = (__nv_bfloat16*)smraw;       // [64][264]
    __nv_bfloat16* Bs0 = As + KM * KSTR;              // 2 x [128][264]
    float* Ssc = (float*)(Bs0 + 2 * KN * KSTR);       // [64][132]
    float* sqm = Ssc + KM * SSTR;                     // 2 x [128]
    float* sqr = sqm + 2 * KN;                        // [64]

    const int tid = threadIdx.x;
    const int b   = blockIdx.y;
    const int n0  = blockIdx.x * KM;
    const uint4* __restrict__ abG = (const uint4*)g_ab;

    const uint32_t bsAddr0  = (uint32_t)__cvta_generic_to_shared(Bs0);
    const uint32_t sqmAddr0 = (uint32_t)__cvta_generic_to_shared(sqm);

    // prologue: start chunk 0 load, then fill A block + sqr
    knn_issueB(b, 0, bsAddr0, sqmAddr0, tid);

    for (int i = tid; i < KM * 32; i += 256) {
        int r = i >> 5, j = i & 31;
        ((uint4*)As)[r * 33 + j] = abG[(size_t)(b * NPTS + n0 + r) * 32 + j];
    }
    if (tid < KM) sqr[tid] = g_sq[b * NPTS + n0 + tid];

    const int wid = tid >> 5, l = tid & 31;
    const int wm = wid & 1, wn = wid >> 1;   // 2x4 warp grid, warp tile 32x32
    const int g = l >> 2, t = l & 3;
    const int rB = tid >> 2, cs = tid & 3;   // phase B: 4 threads per row

    unsigned long long tk[9];
    #pragma unroll
    for (int i = 0; i < 9; ++i) tk[i] = 0ull;

    const uint32_t* Asw = (const uint32_t*)As;
    const int arBase = wm * 32 + g;
    const int bcBase = wn * 32 + g;

    for (int chunk = 0; chunk < NPTS / KN; ++chunk) {
        const int cur = chunk & 1;
        const int m0  = chunk * KN;

        CP_WAIT0();          // buf[cur] + sqm[cur] resident
        __syncthreads();     // all threads see it; all done with buf[1-cur] & prev Ssc

        if (chunk + 1 < NPTS / KN)   // overlap next load with MMA+scatter+topk
            knn_issueB(b, m0 + KN,
                       bsAddr0 + (unsigned)(1 - cur) * KN * KSTR * 2,
                       sqmAddr0 + (unsigned)(1 - cur) * KN * 4, tid);

        const uint32_t* Bsw = (const uint32_t*)(Bs0 + cur * KN * KSTR);
        const float* sqc = sqm + cur * KN;

        float acc[2][4][4];
        #pragma unroll
        for (int mi = 0; mi < 2; ++mi)
            #pragma unroll
            for (int ni = 0; ni < 4; ++ni)
                #pragma unroll
                for (int q = 0; q < 4; ++q) acc[mi][ni][q] = 0.f;

        mma_block(acc, Asw, Bsw, arBase, bcBase, t);

        // scatter final distance values (2*inner - sq_r - sq_m) to score smem
        #pragma unroll
        for (int mi = 0; mi < 2; ++mi) {
            int r = wm * 32 + mi * 16 + g;
            float sr0 = sqr[r], sr1 = sqr[r + 8];
            #pragma unroll
            for (int ni = 0; ni < 4; ++ni) {
                int c = wn * 32 + ni * 8 + t * 2;
                float2 sm2 = *(const float2*)&sqc[c];
                float* a = acc[mi][ni];
                *(float2*)&Ssc[r * SSTR + c] =
                    make_float2(fmaf(2.f, a[0], -sr0 - sm2.x), fmaf(2.f, a[1], -sr0 - sm2.y));
                *(float2*)&Ssc[(r + 8) * SSTR + c] =
                    make_float2(fmaf(2.f, a[2], -sr1 - sm2.x), fmaf(2.f, a[3], -sr1 - sm2.y));
            }
        }
        __syncthreads();

        // per-thread top-9 over 32 cols of its row (float4 reads)
        #pragma unroll
        for (int j4 = 0; j4 < 8; ++j4) {
            int m = cs * 32 + j4 * 4;
            float4 v = *(const float4*)&Ssc[rB * SSTR + m];
            float vv[4] = {v.x, v.y, v.z, v.w};
            #pragma unroll
            for (int q = 0; q < 4; ++q) {
                unsigned long long key = packKey(vv[q], (unsigned)(m0 + m + q));
                if (key > tk[8]) {
                    #pragma unroll
                    for (int i = 0; i < 9; ++i) {
                        unsigned long long a = tk[i];
                        bool gr = key > a;
                        tk[i] = gr ? key : a;
                        key   = gr ? a : key;
                    }
                }
            }
        }
    }

    // merge top-9 across the 4 threads owning each row
    const int row = n0 + rB;
    for (int k = 0; k < KNB; ++k) {
        unsigned long long m = tk[0];
        #pragma unroll
        for (int d = 2; d; d >>= 1) {
            unsigned long long o = __shfl_down_sync(0xffffffffu, m, d, 4);
            if (o > m) m = o;
        }
        m = __shfl_sync(0xffffffffu, m, 0, 4);
        if (tk[0] == m) {   // keys unique (idx embedded): exactly one lane pops
            #pragma unroll
            for (int i = 0; i < 8; ++i) tk[i] = tk[i + 1];
            tk[8] = 0ull;
        }
        if (cs == 0)
            g_nn[(b * NPTS + row) * KNB + k] = (int)(0xFFFFFFFFu - (unsigned)m);
    }
}

// ---------------- p/q GEMM on tensor cores: y[b][n][o] = (wct[o] . xn[n]) * nrm[n] ----------------
__device__ __forceinline__ void gemm_issueW(int o0, uint32_t bsAddr, int tid) {
    const uint4* wbG = (const uint4*)g_wb;
    #pragma unroll 4
    for (int i = tid; i < KN * 32; i += 256) {
        int r = i >> 5, j = i & 31;
        cp16(bsAddr + (unsigned)(r * 33 + j) * 16, wbG + (size_t)(o0 + r) * 32 + j);
    }
    CP_COMMIT();
}

__global__ void __launch_bounds__(256, 1)
gemm_kernel() {
    extern __shared__ char smraw[];
    __nv_bfloat16* As  = (__nv_bfloat16*)smraw;       // [64][264]  (points)
    __nv_bfloat16* Bs0 = As + KM * KSTR;              // 2 x [128][264] (wct)
    float* nrmr = (float*)(Bs0 + 2 * KN * KSTR);      // [64]

    const int tid = threadIdx.x;
    const int b   = blockIdx.y;
    const int n0  = blockIdx.x * KM;
    const uint4* __restrict__ abG = (const uint4*)g_ab;

    const uint32_t bsAddr0 = (uint32_t)__cvta_generic_to_shared(Bs0);
    gemm_issueW(0, bsAddr0, tid);

    for (int i = tid; i < KM * 32; i += 256) {
        int r = i >> 5, j = i & 31;
        ((uint4*)As)[r * 33 + j] = abG[(size_t)(b * NPTS + n0 + r) * 32 + j];
    }
    if (tid < KM) nrmr[tid] = g_nrm[b * NPTS + n0 + tid];

    const int wid = tid >> 5, l = tid & 31;
    const int wm = wid & 1, wn = wid >> 1;
    const int g = l >> 2, t = l & 3;

    const uint32_t* Asw = (const uint32_t*)As;
    const int arBase = wm * 32 + g;
    const int bcBase = wn * 32 + g;
    float* yb = g_y + (size_t)b * NPTS * OC2;

    for (int chunk = 0; chunk < OC2 / KN; ++chunk) {
        const int cur = chunk & 1;
        CP_WAIT0();
        __syncthreads();
        if (chunk + 1 < OC2 / KN)
            gemm_issueW((chunk + 1) * KN, bsAddr0 + (unsigned)(1 - cur) * KN * KSTR * 2, tid);

        const uint32_t* Bsw = (const uint32_t*)(Bs0 + cur * KN * KSTR);

        float acc[2][4][4];
        #pragma unroll
        for (int mi = 0; mi < 2; ++mi)
            #pragma unroll
            for (int ni = 0; ni < 4; ++ni)
                #pragma unroll
                for (int q = 0; q < 4; ++q) acc[mi][ni][q] = 0.f;

        mma_block(acc, Asw, Bsw, arBase, bcBase, t);

        const int oc = chunk * KN;
        #pragma unroll
        for (int mi = 0; mi < 2; ++mi) {
            int r = wm * 32 + mi * 16 + g;
            float nr0 = nrmr[r], nr1 = nrmr[r + 8];
            #pragma unroll
            for (int ni = 0; ni < 4; ++ni) {
                int c = wn * 32 + ni * 8 + t * 2;
                float* a = acc[mi][ni];
                *(float2*)&yb[(size_t)(n0 + r) * OC2 + oc + c] =
                    make_float2(a[0] * nr0, a[1] * nr0);
                *(float2*)&yb[(size_t)(n0 + r + 8) * OC2 + oc + c] =
                    make_float2(a[2] * nr1, a[3] * nr1);
            }
        }
        __syncthreads();   // writes done before Bsw[cur] reused two chunks later
    }
}

// ---------------- epilogue: gather + max + relu ----------------
__global__ void final_kernel(const float* __restrict__ bias, float* __restrict__ out) {
    __shared__ int sj[KNB];
    const int n = blockIdx.x;
    const int b = blockIdx.y;
    const int o = threadIdx.x;
    if (o < KNB) sj[o] = g_nn[(b * NPTS + n) * KNB + o];
    __syncthreads();
    const float* yb = g_y + (size_t)b * NPTS * OC2;
    float p = yb[(size_t)n * OC2 + o];
    float best = -3.4e38f;
    #pragma unroll
    for (int k = 0; k < KNB; ++k)
        best = fmaxf(best, yb[(size_t)sj[k] * OC2 + OC + o]);
    float v = fmaxf(p + best + bias[o], 0.f);
    out[((size_t)b * OC + o) * NPTS + n] = v;
}

// ---------------- launch ----------------
extern "C" void kernel_launch(void* const* d_in, const int* in_sizes, int n_in,
                              void* d_out, int out_size) {
    const float* x    = (const float*)d_in[0];
    const float* w    = (const float*)d_in[1];
    const float* bias = (const float*)d_in[2];
    float* out = (float*)d_out;

    const int prep_smem = (128 * 129 + 128) * (int)sizeof(float);                  // 66560
    const int knn_smem  = KM*KSTR*2 + 2*KN*KSTR*2 + (KM*SSTR + 2*KN + KM) * 4;     // 204032
    const int gemm_smem = KM*KSTR*2 + 2*KN*KSTR*2 + KM * 4;                        // 169216
    cudaFuncSetAttribute(prep_kernel, cudaFuncAttributeMaxDynamicSharedMemorySize, prep_smem);
    cudaFuncSetAttribute(knn_kernel,  cudaFuncAttributeMaxDynamicSharedMemorySize, knn_smem);
    cudaFuncSetAttribute(gemm_kernel, cudaFuncAttributeMaxDynamicSharedMemorySize, gemm_smem);

    prep_kernel <<<dim3(NPTS / 128, BB), 128, prep_smem>>>(x);
    wprep_kernel<<<(OC2 * CCH + 255) / 256, 256>>>(w);
    knn_kernel  <<<dim3(NPTS / KM, BB), 256, knn_smem>>>();
    gemm_kernel <<<dim3(NPTS / KM, BB), 256, gemm_smem>>>();
    final_kernel<<<dim3(NPTS, BB), 256>>>(bias, out);
}